// round 8
// baseline (speedup 1.0000x reference)
#include <cuda_runtime.h>

#define NN 20000
#define DD 32
#define TM 64            // nodes per LSTM block (8 per warp)
#define HSTR 66          // EVEN stride: float2-aligned reads; 2-way write conflict only

typedef unsigned long long ull;

// ---------------- scratch (static device globals; no allocation) ----------------
__device__ float g_Z[NN * 256];     // per-layer input projection + biases
__device__ float g_hA[NN * 64];
__device__ float g_hB[NN * 64];
__device__ float g_agg[NN * 64];
__device__ int   g_snbr[NN * DD];

// ---------------- helpers ----------------
__device__ __forceinline__ ull pack2(float lo, float hi) {
    ull d; asm("mov.b64 %0, {%1,%2};" : "=l"(d) : "f"(lo), "f"(hi)); return d;
}
__device__ __forceinline__ void unpack2(ull v, float& lo, float& hi) {
    asm("mov.b64 {%0,%1}, %2;" : "=f"(lo), "=f"(hi) : "l"(v));
}
__device__ __forceinline__ ull fma2(ull a, ull b, ull c) {
    ull d; asm("fma.rn.f32x2 %0, %1, %2, %3;" : "=l"(d) : "l"(a), "l"(b), "l"(c)); return d;
}
__device__ __forceinline__ float sigf(float x) {
    return __fdividef(1.0f, 1.0f + __expf(-x));
}
__device__ __forceinline__ float tanha(float x) {
    return __fdividef(2.0f, 1.0f + __expf(-2.0f * x)) - 1.0f;
}
__device__ __forceinline__ const float* sel_h(const float* ext, int s) {
    return s == 0 ? g_hA : (s == 1 ? g_hB : ext);
}

// ---------------- 1) per-row bitonic sort of 32 neighbor ids (warp per node) ----------------
__global__ void sort_kernel(const int* __restrict__ nbr) {
    int lane = threadIdx.x & 31;
    int node = (blockIdx.x * blockDim.x + threadIdx.x) >> 5;
    if (node >= NN) return;
    int v = nbr[node * DD + lane];
#pragma unroll
    for (int k = 2; k <= 32; k <<= 1) {
        for (int j = k >> 1; j > 0; j >>= 1) {
            int o = __shfl_xor_sync(0xffffffffu, v, j);
            bool up = ((lane & k) == 0);
            bool lower = ((lane & j) == 0);
            int mn = min(v, o), mx = max(v, o);
            v = (up == lower) ? mn : mx;
        }
    }
    g_snbr[node * DD + lane] = v;
}

// ---------------- 2) Z = h @ W_ih^T + b_ih + b_hh   ([N,256]) ----------------
#define ZNB 16
__global__ void z_kernel(const float* __restrict__ hext, int hselv,
                         const float* __restrict__ Wih,
                         const float* __restrict__ bih,
                         const float* __restrict__ bhh, int in_d) {
    extern __shared__ float sm[];
    float* Ws = sm;                 // [in_d][256], transposed
    float* hs = sm + in_d * 256;    // [ZNB][in_d]
    const float* hin = sel_h(hext, hselv);
    int tid = threadIdx.x;
    int base = blockIdx.x * ZNB;

    for (int idx = tid; idx < in_d * 256; idx += 256) {
        int col = idx & 255, k = idx >> 8;
        Ws[idx] = Wih[col * in_d + k];
    }
    for (int idx = tid; idx < ZNB * in_d; idx += 256) {
        int n = idx / in_d, k = idx - n * in_d;
        int gn = base + n;
        hs[idx] = (gn < NN) ? hin[gn * in_d + k] : 0.0f;
    }
    __syncthreads();

    int col = tid;
    float bias = bih[col] + bhh[col];
    float acc[ZNB];
#pragma unroll
    for (int n = 0; n < ZNB; n++) acc[n] = bias;
    for (int k = 0; k < in_d; k++) {
        float w = Ws[k * 256 + col];
#pragma unroll
        for (int n = 0; n < ZNB; n++) acc[n] += hs[n * in_d + k] * w;
    }
#pragma unroll
    for (int n = 0; n < ZNB; n++) {
        int gn = base + n;
        if (gn < NN) g_Z[gn * 256 + col] = acc[n];
    }
}

// ---------------- 3) recurrent LSTM over 32 neighbor steps ----------------
// 256 threads: tx in [0,32) covers units (tx, tx+32) packed in f32x2;
// warp ty in [0,8) covers 8 nodes. Double-buffered h tile, one barrier/step.
// Occupancy 2 target: smem 107,520 B, regs capped at 128.
__global__ __launch_bounds__(256, 2)
void lstm_kernel(const float* __restrict__ Whh) {
    extern __shared__ float sm[];
    float2* Wp = (float2*)sm;             // [64k][4g][32tx] = (W[g*64+tx][k], W[g*64+tx+32][k]) 64KB
    float* hs = sm + 16384;               // [2 buf][64 unit][HSTR nodes] 33.79KB
    int* sn = (int*)(hs + 2 * 64 * HSTR); // [TM][32] sorted neighbor ids 8KB

    int tid = threadIdx.x;
    int tx = tid & 31, ty = tid >> 5;
    int base = blockIdx.x * TM;

    for (int idx = tid; idx < 8192; idx += 256) {
        int txx = idx & 31;
        int g = (idx >> 5) & 3;
        int k = idx >> 7;
        Wp[idx] = make_float2(Whh[(g * 64 + txx) * 64 + k],
                              Whh[(g * 64 + txx + 32) * 64 + k]);
    }
    for (int idx = tid; idx < 64 * HSTR; idx += 256) hs[idx] = 0.0f;  // buffer 0 (read at t=0)
    for (int idx = tid; idx < TM * DD; idx += 256) {
        int n = idx >> 5, d = idx & 31;
        int gn = base + n;
        sn[idx] = (gn < NN) ? g_snbr[gn * DD + d] : 0;
    }
    __syncthreads();

    const int nb = ty * 8;
    float c0[8], c1[8];
#pragma unroll
    for (int i = 0; i < 8; i++) { c0[i] = 0.0f; c1[i] = 0.0f; }

#pragma unroll 1
    for (int t = 0; t < DD; t++) {
        const float* hr = hs + (t & 1) * (64 * HSTR);
        float* hw = hs + ((t & 1) ^ 1) * (64 * HSTR);

        ull acc2[8][4];
#pragma unroll
        for (int i = 0; i < 8; i++)
#pragma unroll
            for (int g = 0; g < 4; g++) acc2[i][g] = 0ull;

        // gates += h_prev @ W_hh^T  (f32x2: unit halves tx / tx+32 packed)
        // k*HSTR + nb is always EVEN (HSTR even, nb even) -> float2 loads 8B-aligned.
#pragma unroll 4
        for (int k = 0; k < 64; k++) {
            float2 ha = *(const float2*)&hr[k * HSTR + nb + 0];
            float2 hb = *(const float2*)&hr[k * HSTR + nb + 2];
            float2 hc = *(const float2*)&hr[k * HSTR + nb + 4];
            float2 hd = *(const float2*)&hr[k * HSTR + nb + 6];
            ull h2[8];
            h2[0] = pack2(ha.x, ha.x); h2[1] = pack2(ha.y, ha.y);
            h2[2] = pack2(hb.x, hb.x); h2[3] = pack2(hb.y, hb.y);
            h2[4] = pack2(hc.x, hc.x); h2[5] = pack2(hc.y, hc.y);
            h2[6] = pack2(hd.x, hd.x); h2[7] = pack2(hd.y, hd.y);
            ull w2[4];
#pragma unroll
            for (int g = 0; g < 4; g++) w2[g] = *(const ull*)&Wp[(k * 4 + g) * 32 + tx];
#pragma unroll
            for (int i = 0; i < 8; i++)
#pragma unroll
                for (int g = 0; g < 4; g++) acc2[i][g] = fma2(h2[i], w2[g], acc2[i][g]);
        }

        // gather Z row of step-t neighbor, apply LSTM cell, write h to other buffer
#pragma unroll
        for (int i = 0; i < 8; i++) {
            int r = sn[(nb + i) * DD + t];
            const float* zr = g_Z + r * 256;
            float a0, a1, f0, f1, gg0, gg1, o0, o1;
            unpack2(acc2[i][0], a0, a1);
            unpack2(acc2[i][1], f0, f1);
            unpack2(acc2[i][2], gg0, gg1);
            unpack2(acc2[i][3], o0, o1);
            a0 += zr[tx];        a1 += zr[32 + tx];
            f0 += zr[64 + tx];   f1 += zr[96 + tx];
            gg0 += zr[128 + tx]; gg1 += zr[160 + tx];
            o0 += zr[192 + tx];  o1 += zr[224 + tx];
            float cc = sigf(f0) * c0[i] + sigf(a0) * tanha(gg0);
            c0[i] = cc;
            float hh0 = sigf(o0) * tanha(cc);
            cc = sigf(f1) * c1[i] + sigf(a1) * tanha(gg1);
            c1[i] = cc;
            float hh1 = sigf(o1) * tanha(cc);
            hw[tx * HSTR + nb + i] = hh0;          // lane stride 66 -> 2-way conflict (minor)
            hw[(tx + 32) * HSTR + nb + i] = hh1;
            if (t == DD - 1) {
                int gn = base + nb + i;
                if (gn < NN) {
                    g_agg[gn * 64 + tx] = hh0;
                    g_agg[gn * 64 + 32 + tx] = hh1;
                }
            }
        }
        __syncthreads();   // h_t visible before next step's GEMM reads
    }
}

// ---------------- 4) h_out = relu([h_in, agg] @ Wl^T + bl) ----------------
#define CNB 32
__global__ void combine_kernel(const float* __restrict__ hext, int hselv,
                               const float* __restrict__ Wl,
                               const float* __restrict__ bl,
                               int oselv, int in_d) {
    int K = in_d + 64;
    extern __shared__ float sm[];
    float* Wls = sm;               // [K][64] transposed
    float* cats = sm + K * 64;     // [CNB][K]
    const float* hin = sel_h(hext, hselv);
    float* hout = (oselv == 0) ? g_hA : g_hB;

    int tid = threadIdx.x;
    int j = tid & 63;
    int grp = tid >> 6;            // 4 groups x 8 nodes
    int base = blockIdx.x * CNB;

    for (int idx = tid; idx < K * 64; idx += 256) {
        int k = idx >> 6, j2 = idx & 63;
        Wls[idx] = Wl[j2 * K + k];
    }
    for (int idx = tid; idx < CNB * K; idx += 256) {
        int n = idx / K, k = idx - n * K;
        int gn = base + n;
        float v = 0.0f;
        if (gn < NN) v = (k < in_d) ? hin[gn * in_d + k] : g_agg[gn * 64 + (k - in_d)];
        cats[idx] = v;
    }
    __syncthreads();

    float acc[8];
#pragma unroll
    for (int i = 0; i < 8; i++) acc[i] = 0.0f;
    for (int k = 0; k < K; k++) {
        float w = Wls[k * 64 + j];
#pragma unroll
        for (int i = 0; i < 8; i++) acc[i] += cats[(grp * 8 + i) * K + k] * w;
    }
    float bj = bl[j];
#pragma unroll
    for (int i = 0; i < 8; i++) {
        int gn = base + grp * 8 + i;
        if (gn < NN) hout[gn * 64 + j] = fmaxf(acc[i] + bj, 0.0f);
    }
}

// ---------------- 5) out = h @ W_out^T + b_out  (warp per node) ----------------
__global__ void out_kernel(int hselv, const float* __restrict__ Wout,
                           const float* __restrict__ bout, float* __restrict__ out) {
    const float* hin = sel_h(nullptr, hselv);
    int lane = threadIdx.x & 31;
    int node = (blockIdx.x * blockDim.x + threadIdx.x) >> 5;
    if (node >= NN) return;
    float s = hin[node * 64 + lane] * Wout[lane] + hin[node * 64 + 32 + lane] * Wout[32 + lane];
#pragma unroll
    for (int d = 16; d > 0; d >>= 1) s += __shfl_xor_sync(0xffffffffu, s, d);
    if (lane == 0) out[node] = s + bout[0];
}

// ---------------- launcher ----------------
extern "C" void kernel_launch(void* const* d_in, const int* in_sizes, int n_in,
                              void* d_out, int out_size) {
    const float* nf = (const float*)d_in[0];
    const int* nbr = (const int*)d_in[1];
    const float* Wih[3] = {(const float*)d_in[2], (const float*)d_in[8], (const float*)d_in[14]};
    const float* Whh[3] = {(const float*)d_in[3], (const float*)d_in[9], (const float*)d_in[15]};
    const float* bih[3] = {(const float*)d_in[4], (const float*)d_in[10], (const float*)d_in[16]};
    const float* bhh[3] = {(const float*)d_in[5], (const float*)d_in[11], (const float*)d_in[17]};
    const float* Wl[3]  = {(const float*)d_in[6], (const float*)d_in[12], (const float*)d_in[18]};
    const float* bl[3]  = {(const float*)d_in[7], (const float*)d_in[13], (const float*)d_in[19]};
    const float* Wout = (const float*)d_in[20];
    const float* bout = (const float*)d_in[21];
    float* out = (float*)d_out;

    size_t lsm = 65536 + (size_t)2 * 64 * HSTR * 4 + (size_t)TM * DD * 4;   // 107,520

    cudaFuncSetAttribute(z_kernel, cudaFuncAttributeMaxDynamicSharedMemorySize, 72 * 1024);
    cudaFuncSetAttribute(lstm_kernel, cudaFuncAttributeMaxDynamicSharedMemorySize, (int)lsm);
    cudaFuncSetAttribute(combine_kernel, cudaFuncAttributeMaxDynamicSharedMemorySize, 50 * 1024);

    sort_kernel<<<(NN * 32 + 255) / 256, 256>>>(nbr);

    int hsel = 2;   // external (node_features)
    for (int l = 0; l < 3; l++) {
        int in_d = (l == 0) ? 3 : 64;
        size_t zsm = (size_t)(in_d * 256 + ZNB * in_d) * 4;
        z_kernel<<<(NN + ZNB - 1) / ZNB, 256, zsm>>>(nf, hsel, Wih[l], bih[l], bhh[l], in_d);

        lstm_kernel<<<(NN + TM - 1) / TM, 256, lsm>>>(Whh[l]);

        int K = in_d + 64;
        size_t csm = (size_t)(K * 64 + CNB * K) * 4;
        int osel = (l & 1) ? 1 : 0;   // l0 -> hA, l1 -> hB, l2 -> hA
        combine_kernel<<<(NN + CNB - 1) / CNB, 256, csm>>>(nf, hsel, Wl[l], bl[l], osel, in_d);
        hsel = osel;
    }

    out_kernel<<<(NN * 32 + 255) / 256, 256>>>(hsel, Wout, bout, out);
}

// round 9
// speedup vs baseline: 1.2488x; 1.2488x over previous
#include <cuda_runtime.h>

#define NN 20000
#define DD 32
#define TM 48            // nodes per LSTM block (6 per warp) — small reg footprint for occ 2
#define HSTR 66          // EVEN stride: float2-aligned reads; 2-way write conflict only

typedef unsigned long long ull;

// ---------------- scratch (static device globals; no allocation) ----------------
__device__ float g_Z[NN * 256];     // per-layer input projection + biases
__device__ float g_hA[NN * 64];
__device__ float g_hB[NN * 64];
__device__ float g_agg[NN * 64];
__device__ int   g_snbr[NN * DD];

// ---------------- helpers ----------------
__device__ __forceinline__ ull pack2(float lo, float hi) {
    ull d; asm("mov.b64 %0, {%1,%2};" : "=l"(d) : "f"(lo), "f"(hi)); return d;
}
__device__ __forceinline__ void unpack2(ull v, float& lo, float& hi) {
    asm("mov.b64 {%0,%1}, %2;" : "=f"(lo), "=f"(hi) : "l"(v));
}
__device__ __forceinline__ ull fma2(ull a, ull b, ull c) {
    ull d; asm("fma.rn.f32x2 %0, %1, %2, %3;" : "=l"(d) : "l"(a), "l"(b), "l"(c)); return d;
}
__device__ __forceinline__ float tanhf_a(float x) {
    float r; asm("tanh.approx.f32 %0, %1;" : "=f"(r) : "f"(x)); return r;
}
__device__ __forceinline__ float sigf(float x) {        // 1 MUFU + 1 FMA
    return fmaf(tanhf_a(0.5f * x), 0.5f, 0.5f);
}
__device__ __forceinline__ const float* sel_h(const float* ext, int s) {
    return s == 0 ? g_hA : (s == 1 ? g_hB : ext);
}

// ---------------- 1) per-row bitonic sort of 32 neighbor ids (warp per node) ----------------
__global__ void sort_kernel(const int* __restrict__ nbr) {
    int lane = threadIdx.x & 31;
    int node = (blockIdx.x * blockDim.x + threadIdx.x) >> 5;
    if (node >= NN) return;
    int v = nbr[node * DD + lane];
#pragma unroll
    for (int k = 2; k <= 32; k <<= 1) {
        for (int j = k >> 1; j > 0; j >>= 1) {
            int o = __shfl_xor_sync(0xffffffffu, v, j);
            bool up = ((lane & k) == 0);
            bool lower = ((lane & j) == 0);
            int mn = min(v, o), mx = max(v, o);
            v = (up == lower) ? mn : mx;
        }
    }
    g_snbr[node * DD + lane] = v;
}

// ---------------- 2) Z = h @ W_ih^T + b_ih + b_hh   ([N,256]) ----------------
#define ZNB 16
__global__ void z_kernel(const float* __restrict__ hext, int hselv,
                         const float* __restrict__ Wih,
                         const float* __restrict__ bih,
                         const float* __restrict__ bhh, int in_d) {
    extern __shared__ float sm[];
    float* Ws = sm;                 // [in_d][256], transposed
    float* hs = sm + in_d * 256;    // [ZNB][in_d]
    const float* hin = sel_h(hext, hselv);
    int tid = threadIdx.x;
    int base = blockIdx.x * ZNB;

    for (int idx = tid; idx < in_d * 256; idx += 256) {
        int col = idx & 255, k = idx >> 8;
        Ws[idx] = Wih[col * in_d + k];
    }
    for (int idx = tid; idx < ZNB * in_d; idx += 256) {
        int n = idx / in_d, k = idx - n * in_d;
        int gn = base + n;
        hs[idx] = (gn < NN) ? hin[gn * in_d + k] : 0.0f;
    }
    __syncthreads();

    int col = tid;
    float bias = bih[col] + bhh[col];
    float acc[ZNB];
#pragma unroll
    for (int n = 0; n < ZNB; n++) acc[n] = bias;
    for (int k = 0; k < in_d; k++) {
        float w = Ws[k * 256 + col];
#pragma unroll
        for (int n = 0; n < ZNB; n++) acc[n] += hs[n * in_d + k] * w;
    }
#pragma unroll
    for (int n = 0; n < ZNB; n++) {
        int gn = base + n;
        if (gn < NN) g_Z[gn * 256 + col] = acc[n];
    }
}

// ---------------- 3) recurrent LSTM over 32 neighbor steps ----------------
// 256 threads: tx in [0,32) covers units (tx, tx+32) packed in f32x2;
// warp ty in [0,8) covers 6 nodes. Double-buffered h tile, one barrier/step.
// Occupancy 2: smem 105,472 B/block (x2 = 211KB <= 227KB), ~95 live regs < 128 cap.
__global__ __launch_bounds__(256, 2)
void lstm_kernel(const float* __restrict__ Whh) {
    extern __shared__ float sm[];
    float2* Wp = (float2*)sm;             // [64k][4g][32tx] = (W[g*64+tx][k], W[g*64+tx+32][k]) 64KB
    float* hs = sm + 16384;               // [2 buf][64 unit][HSTR nodes] 33.79KB
    int* sn = (int*)(hs + 2 * 64 * HSTR); // [TM][32] sorted neighbor ids 6KB

    int tid = threadIdx.x;
    int tx = tid & 31, ty = tid >> 5;
    int base = blockIdx.x * TM;

    for (int idx = tid; idx < 8192; idx += 256) {
        int txx = idx & 31;
        int g = (idx >> 5) & 3;
        int k = idx >> 7;
        Wp[idx] = make_float2(Whh[(g * 64 + txx) * 64 + k],
                              Whh[(g * 64 + txx + 32) * 64 + k]);
    }
    for (int idx = tid; idx < 64 * HSTR; idx += 256) hs[idx] = 0.0f;  // buffer 0 (read at t=0)
    for (int idx = tid; idx < TM * DD; idx += 256) {
        int n = idx >> 5, d = idx & 31;
        int gn = base + n;
        sn[idx] = (gn < NN) ? g_snbr[gn * DD + d] : 0;
    }
    __syncthreads();

    const int nb = ty * 6;   // even -> float2-aligned with even HSTR
    float c0[6], c1[6];
#pragma unroll
    for (int i = 0; i < 6; i++) { c0[i] = 0.0f; c1[i] = 0.0f; }

#pragma unroll 1
    for (int t = 0; t < DD; t++) {
        const float* hr = hs + (t & 1) * (64 * HSTR);
        float* hw = hs + ((t & 1) ^ 1) * (64 * HSTR);

        ull acc2[6][4];
#pragma unroll
        for (int i = 0; i < 6; i++)
#pragma unroll
            for (int g = 0; g < 4; g++) acc2[i][g] = 0ull;

        // gates += h_prev @ W_hh^T  (f32x2: unit halves tx / tx+32 packed)
#pragma unroll 4
        for (int k = 0; k < 64; k++) {
            float2 ha = *(const float2*)&hr[k * HSTR + nb + 0];
            float2 hb = *(const float2*)&hr[k * HSTR + nb + 2];
            float2 hc = *(const float2*)&hr[k * HSTR + nb + 4];
            ull h2[6];
            h2[0] = pack2(ha.x, ha.x); h2[1] = pack2(ha.y, ha.y);
            h2[2] = pack2(hb.x, hb.x); h2[3] = pack2(hb.y, hb.y);
            h2[4] = pack2(hc.x, hc.x); h2[5] = pack2(hc.y, hc.y);
            ull w2[4];
#pragma unroll
            for (int g = 0; g < 4; g++) w2[g] = *(const ull*)&Wp[(k * 4 + g) * 32 + tx];
#pragma unroll
            for (int i = 0; i < 6; i++)
#pragma unroll
                for (int g = 0; g < 4; g++) acc2[i][g] = fma2(h2[i], w2[g], acc2[i][g]);
        }

        // gather Z row of step-t neighbor, apply LSTM cell (tanh.approx), write h
#pragma unroll
        for (int i = 0; i < 6; i++) {
            int r = sn[(nb + i) * DD + t];
            const float* zr = g_Z + r * 256;
            float a0, a1, f0, f1, gg0, gg1, o0, o1;
            unpack2(acc2[i][0], a0, a1);
            unpack2(acc2[i][1], f0, f1);
            unpack2(acc2[i][2], gg0, gg1);
            unpack2(acc2[i][3], o0, o1);
            a0 += zr[tx];        a1 += zr[32 + tx];
            f0 += zr[64 + tx];   f1 += zr[96 + tx];
            gg0 += zr[128 + tx]; gg1 += zr[160 + tx];
            o0 += zr[192 + tx];  o1 += zr[224 + tx];
            float cc = sigf(f0) * c0[i] + sigf(a0) * tanhf_a(gg0);
            c0[i] = cc;
            float hh0 = sigf(o0) * tanhf_a(cc);
            cc = sigf(f1) * c1[i] + sigf(a1) * tanhf_a(gg1);
            c1[i] = cc;
            float hh1 = sigf(o1) * tanhf_a(cc);
            hw[tx * HSTR + nb + i] = hh0;          // 2-way bank conflict only (stride 66)
            hw[(tx + 32) * HSTR + nb + i] = hh1;
            if (t == DD - 1) {
                int gn = base + nb + i;
                if (gn < NN) {
                    g_agg[gn * 64 + tx] = hh0;
                    g_agg[gn * 64 + 32 + tx] = hh1;
                }
            }
        }
        __syncthreads();   // h_t visible before next step's GEMM reads
    }
}

// ---------------- 4) h_out = relu([h_in, agg] @ Wl^T + bl) ----------------
#define CNB 32
__global__ void combine_kernel(const float* __restrict__ hext, int hselv,
                               const float* __restrict__ Wl,
                               const float* __restrict__ bl,
                               int oselv, int in_d) {
    int K = in_d + 64;
    extern __shared__ float sm[];
    float* Wls = sm;               // [K][64] transposed
    float* cats = sm + K * 64;     // [CNB][K]
    const float* hin = sel_h(hext, hselv);
    float* hout = (oselv == 0) ? g_hA : g_hB;

    int tid = threadIdx.x;
    int j = tid & 63;
    int grp = tid >> 6;            // 4 groups x 8 nodes
    int base = blockIdx.x * CNB;

    for (int idx = tid; idx < K * 64; idx += 256) {
        int k = idx >> 6, j2 = idx & 63;
        Wls[idx] = Wl[j2 * K + k];
    }
    for (int idx = tid; idx < CNB * K; idx += 256) {
        int n = idx / K, k = idx - n * K;
        int gn = base + n;
        float v = 0.0f;
        if (gn < NN) v = (k < in_d) ? hin[gn * in_d + k] : g_agg[gn * 64 + (k - in_d)];
        cats[idx] = v;
    }
    __syncthreads();

    float acc[8];
#pragma unroll
    for (int i = 0; i < 8; i++) acc[i] = 0.0f;
    for (int k = 0; k < K; k++) {
        float w = Wls[k * 64 + j];
#pragma unroll
        for (int i = 0; i < 8; i++) acc[i] += cats[(grp * 8 + i) * K + k] * w;
    }
    float bj = bl[j];
#pragma unroll
    for (int i = 0; i < 8; i++) {
        int gn = base + grp * 8 + i;
        if (gn < NN) hout[gn * 64 + j] = fmaxf(acc[i] + bj, 0.0f);
    }
}

// ---------------- 5) out = h @ W_out^T + b_out  (warp per node) ----------------
__global__ void out_kernel(int hselv, const float* __restrict__ Wout,
                           const float* __restrict__ bout, float* __restrict__ out) {
    const float* hin = sel_h(nullptr, hselv);
    int lane = threadIdx.x & 31;
    int node = (blockIdx.x * blockDim.x + threadIdx.x) >> 5;
    if (node >= NN) return;
    float s = hin[node * 64 + lane] * Wout[lane] + hin[node * 64 + 32 + lane] * Wout[32 + lane];
#pragma unroll
    for (int d = 16; d > 0; d >>= 1) s += __shfl_xor_sync(0xffffffffu, s, d);
    if (lane == 0) out[node] = s + bout[0];
}

// ---------------- launcher ----------------
extern "C" void kernel_launch(void* const* d_in, const int* in_sizes, int n_in,
                              void* d_out, int out_size) {
    const float* nf = (const float*)d_in[0];
    const int* nbr = (const int*)d_in[1];
    const float* Wih[3] = {(const float*)d_in[2], (const float*)d_in[8], (const float*)d_in[14]};
    const float* Whh[3] = {(const float*)d_in[3], (const float*)d_in[9], (const float*)d_in[15]};
    const float* bih[3] = {(const float*)d_in[4], (const float*)d_in[10], (const float*)d_in[16]};
    const float* bhh[3] = {(const float*)d_in[5], (const float*)d_in[11], (const float*)d_in[17]};
    const float* Wl[3]  = {(const float*)d_in[6], (const float*)d_in[12], (const float*)d_in[18]};
    const float* bl[3]  = {(const float*)d_in[7], (const float*)d_in[13], (const float*)d_in[19]};
    const float* Wout = (const float*)d_in[20];
    const float* bout = (const float*)d_in[21];
    float* out = (float*)d_out;

    size_t lsm = 65536 + (size_t)2 * 64 * HSTR * 4 + (size_t)TM * DD * 4;   // 105,472

    cudaFuncSetAttribute(z_kernel, cudaFuncAttributeMaxDynamicSharedMemorySize, 72 * 1024);
    cudaFuncSetAttribute(lstm_kernel, cudaFuncAttributeMaxDynamicSharedMemorySize, (int)lsm);
    cudaFuncSetAttribute(combine_kernel, cudaFuncAttributeMaxDynamicSharedMemorySize, 50 * 1024);

    sort_kernel<<<(NN * 32 + 255) / 256, 256>>>(nbr);

    int hsel = 2;   // external (node_features)
    for (int l = 0; l < 3; l++) {
        int in_d = (l == 0) ? 3 : 64;
        size_t zsm = (size_t)(in_d * 256 + ZNB * in_d) * 4;
        z_kernel<<<(NN + ZNB - 1) / ZNB, 256, zsm>>>(nf, hsel, Wih[l], bih[l], bhh[l], in_d);

        lstm_kernel<<<(NN + TM - 1) / TM, 256, lsm>>>(Whh[l]);

        int K = in_d + 64;
        size_t csm = (size_t)(K * 64 + CNB * K) * 4;
        int osel = (l & 1) ? 1 : 0;   // l0 -> hA, l1 -> hB, l2 -> hA
        combine_kernel<<<(NN + CNB - 1) / CNB, 256, csm>>>(nf, hsel, Wl[l], bl[l], osel, in_d);
        hsel = osel;
    }

    out_kernel<<<(NN * 32 + 255) / 256, 256>>>(hsel, Wout, bout, out);
}